// round 6
// baseline (speedup 1.0000x reference)
#include <cuda_runtime.h>
#include <cuda_bf16.h>
#include <math.h>
#include <stdint.h>

#define NV 100000
#define NE 20000
#define CH 128
#define NCLS 40
#define BN_EPS 1e-5f
#define EPAD 256   // max hyperedge degree slot (mean 160, sigma 12.6)
#define VPAD 128   // max vertex degree slot (mean 32, sigma 5.7)

// ---------------- scratch (device globals; no cudaMalloc allowed) ----------------
__device__ static float g_ebuf [(size_t)NE * CH];           // 10.24 MB (agg1 out)
__device__ static float g_ebuf2[(size_t)NE * CH];           // 10.24 MB (gemm128#1 out; agg3 out)
__device__ static float g_vbuf [(size_t)NV * CH];           // 51.2 MB (agg2 out)
__device__ static __nv_bfloat16 g_xh   [(size_t)NV * CH];   // 25.6 MB (x bf16)
__device__ static __nv_bfloat16 g_eh   [(size_t)NE * CH];   // 5.12 MB (gemm128#2 out bf16 -> agg2 src)
__device__ static __nv_bfloat16 g_vb2h [(size_t)NV * NCLS]; // 8 MB (gemm40<128> out -> agg3 src)
__device__ static __nv_bfloat16 g_e40h [(size_t)NE * NCLS]; // 1.6 MB (gemm40<40> out -> agg4 src)
__device__ static int   g_ecnt[NE];
__device__ static int   g_vcnt[NV];
__device__ static int   g_eadj[(size_t)NE * EPAD];          // 20.48 MB
__device__ static int   g_vadj[(size_t)NV * VPAD];          // 51.2 MB

// ---------------- prelude ----------------
__global__ void zero_counts(int* e, int ne, int* v, int nv) {
    int total = ne + nv;
    for (int i = blockIdx.x * blockDim.x + threadIdx.x; i < total; i += gridDim.x * blockDim.x) {
        if (i < ne) e[i] = 0; else v[i - ne] = 0;
    }
}

// Single-pass padded adjacency build (rank = atomic return value).
__global__ void build_padded(const int* __restrict__ v_ids, const int* __restrict__ e_ids,
                             int* ecnt, int* vcnt,
                             int* __restrict__ eadj, int* __restrict__ vadj, int nnz) {
    for (int i = blockIdx.x * blockDim.x + threadIdx.x; i < nnz; i += gridDim.x * blockDim.x) {
        int e = e_ids[i], v = v_ids[i];
        int re = atomicAdd(&ecnt[e], 1);
        if (re < EPAD) eadj[((size_t)e << 8) + re] = v;
        int rv = atomicAdd(&vcnt[v], 1);
        if (rv < VPAD) vadj[((size_t)v << 7) + rv] = e;
    }
}

// fp32 -> bf16 elementwise (n multiple of 4)
__global__ void cvt_bf16(const float* __restrict__ src, __nv_bfloat16* __restrict__ dst, int n) {
    int i = (blockIdx.x * blockDim.x + threadIdx.x) * 4;
    if (i < n) {
        float4 f = *reinterpret_cast<const float4*>(src + i);
        __nv_bfloat162 a = __floats2bfloat162_rn(f.x, f.y);
        __nv_bfloat162 b = __floats2bfloat162_rn(f.z, f.w);
        uint2 o;
        o.x = *reinterpret_cast<uint32_t*>(&a);
        o.y = *reinterpret_cast<uint32_t*>(&b);
        *reinterpret_cast<uint2*>(dst + i) = o;
    }
}

__device__ __forceinline__ void acc_bf16x8(float* acc, uint4 p) {
    const uint32_t* w = &p.x;
    #pragma unroll
    for (int q = 0; q < 4; q++) {
        float2 f = __bfloat1622float2(*reinterpret_cast<const __nv_bfloat162*>(&w[q]));
        acc[q * 2 + 0] += f.x;
        acc[q * 2 + 1] += f.y;
    }
}

// ---------------- agg1: e-side segment mean, bf16 source, 128 ch ----------------
__global__ void __launch_bounds__(128)
seg_agg_h128(const __nv_bfloat16* __restrict__ src, const int* __restrict__ cnt,
             const int* __restrict__ adj, float* __restrict__ dst, int nseg) {
    const int tid = threadIdx.x;
    const int chunk = tid % 16;
    const int rl = tid / 16;
    __shared__ float sacc[8][16][8];

    for (int s = blockIdx.x; s < nseg; s += gridDim.x) {
        int deg = cnt[s]; if (deg > EPAD) deg = EPAD;
        const size_t base = (size_t)s << 8;
        float acc[8];
        #pragma unroll
        for (int k = 0; k < 8; k++) acc[k] = 0.f;

        int j = rl;
        for (; j + 8 < deg; j += 16) {
            int i0 = adj[base + j], i1 = adj[base + j + 8];
            uint4 p0 = *reinterpret_cast<const uint4*>(src + (size_t)i0 * 128 + chunk * 8);
            uint4 p1 = *reinterpret_cast<const uint4*>(src + (size_t)i1 * 128 + chunk * 8);
            acc_bf16x8(acc, p0);
            acc_bf16x8(acc, p1);
        }
        for (; j < deg; j += 8) {
            int i0 = adj[base + j];
            uint4 p0 = *reinterpret_cast<const uint4*>(src + (size_t)i0 * 128 + chunk * 8);
            acc_bf16x8(acc, p0);
        }
        #pragma unroll
        for (int k = 0; k < 8; k++) sacc[rl][chunk][k] = acc[k];
        __syncthreads();
        if (rl == 0) {
            #pragma unroll
            for (int r = 1; r < 8; r++)
                #pragma unroll
                for (int k = 0; k < 8; k++) acc[k] += sacc[r][chunk][k];
            float inv = 1.0f / (float)(deg < 1 ? 1 : deg);
            #pragma unroll
            for (int k = 0; k < 8; k++) acc[k] *= inv;
            float4 o0 = make_float4(acc[0], acc[1], acc[2], acc[3]);
            float4 o1 = make_float4(acc[4], acc[5], acc[6], acc[7]);
            *reinterpret_cast<float4*>(dst + (size_t)s * 128 + chunk * 8) = o0;
            *reinterpret_cast<float4*>(dst + (size_t)s * 128 + chunk * 8 + 4) = o1;
        }
        __syncthreads();
    }
}

// ---------------- agg2: v-side warp-per-segment mean, bf16 source, relu+BN ----------------
// Warp splits into 2 halves; each half covers one incidence (16 lanes x 16B = 256B row).
// Unroll x2 per half; final shfl_xor(16) combine; folded BN in-register.
__global__ void __launch_bounds__(256)
seg_agg2_h128_bn(const __nv_bfloat16* __restrict__ src, const int* __restrict__ cnt,
                 const int* __restrict__ adj, float* __restrict__ dst, int nseg,
                 const float* __restrict__ bng, const float* __restrict__ bnb,
                 const float* __restrict__ bnm, const float* __restrict__ bnv) {
    const int lane = threadIdx.x & 31;
    const int half = lane >> 4;
    const int sub  = lane & 15;
    const int wid = (blockIdx.x * (blockDim.x >> 5)) + (threadIdx.x >> 5);
    const int nw = gridDim.x * (blockDim.x >> 5);

    float sc[8], sh[8];
    #pragma unroll
    for (int k = 0; k < 8; k++) {
        int c = sub * 8 + k;
        float scv = rsqrtf(bnv[c] + BN_EPS) * bng[c];
        sc[k] = scv;
        sh[k] = bnb[c] - bnm[c] * scv;
    }

    for (int s = wid; s < nseg; s += nw) {
        int deg = cnt[s]; if (deg > VPAD) deg = VPAD;
        const size_t base = (size_t)s << 7;
        float acc[8];
        #pragma unroll
        for (int k = 0; k < 8; k++) acc[k] = 0.f;

        int j = half;
        for (; j + 2 < deg; j += 4) {
            int i0 = adj[base + j], i1 = adj[base + j + 2];
            uint4 p0 = *reinterpret_cast<const uint4*>(src + (size_t)i0 * 128 + sub * 8);
            uint4 p1 = *reinterpret_cast<const uint4*>(src + (size_t)i1 * 128 + sub * 8);
            acc_bf16x8(acc, p0);
            acc_bf16x8(acc, p1);
        }
        for (; j < deg; j += 2) {
            int i0 = adj[base + j];
            uint4 p0 = *reinterpret_cast<const uint4*>(src + (size_t)i0 * 128 + sub * 8);
            acc_bf16x8(acc, p0);
        }
        #pragma unroll
        for (int k = 0; k < 8; k++)
            acc[k] += __shfl_xor_sync(0xffffffffu, acc[k], 16);
        if (half == 0) {
            float inv = 1.0f / (float)(deg < 1 ? 1 : deg);
            float o[8];
            #pragma unroll
            for (int k = 0; k < 8; k++)
                o[k] = fmaxf(acc[k] * inv, 0.f) * sc[k] + sh[k];
            float4 o0 = make_float4(o[0], o[1], o[2], o[3]);
            float4 o1 = make_float4(o[4], o[5], o[6], o[7]);
            *reinterpret_cast<float4*>(dst + (size_t)s * 128 + sub * 8) = o0;
            *reinterpret_cast<float4*>(dst + (size_t)s * 128 + sub * 8 + 4) = o1;
        }
    }
}

// ---------------- agg3: e-side segment mean, bf16 source, 40 ch, relu ----------------
__global__ void __launch_bounds__(120)
seg_agg_h40(const __nv_bfloat16* __restrict__ src, const int* __restrict__ cnt,
            const int* __restrict__ adj, float* __restrict__ dst, int nseg) {
    const int tid = threadIdx.x;
    const int chunk = tid % 10;
    const int rl = tid / 10;
    __shared__ float sacc[12][10][4];

    for (int s = blockIdx.x; s < nseg; s += gridDim.x) {
        int deg = cnt[s]; if (deg > EPAD) deg = EPAD;
        const size_t base = (size_t)s << 8;
        float acc[4] = {0.f, 0.f, 0.f, 0.f};

        int j = rl;
        for (; j + 3 * 12 < deg; j += 4 * 12) {
            int i0 = adj[base + j],      i1 = adj[base + j + 12];
            int i2 = adj[base + j + 24], i3 = adj[base + j + 36];
            uint2 p0 = *reinterpret_cast<const uint2*>(src + (size_t)i0 * 40 + chunk * 4);
            uint2 p1 = *reinterpret_cast<const uint2*>(src + (size_t)i1 * 40 + chunk * 4);
            uint2 p2 = *reinterpret_cast<const uint2*>(src + (size_t)i2 * 40 + chunk * 4);
            uint2 p3 = *reinterpret_cast<const uint2*>(src + (size_t)i3 * 40 + chunk * 4);
            #pragma unroll
            for (int q = 0; q < 2; q++) {
                const uint32_t* w0 = &p0.x; const uint32_t* w1 = &p1.x;
                const uint32_t* w2 = &p2.x; const uint32_t* w3 = &p3.x;
                float2 f0 = __bfloat1622float2(*reinterpret_cast<const __nv_bfloat162*>(&w0[q]));
                float2 f1 = __bfloat1622float2(*reinterpret_cast<const __nv_bfloat162*>(&w1[q]));
                float2 f2 = __bfloat1622float2(*reinterpret_cast<const __nv_bfloat162*>(&w2[q]));
                float2 f3 = __bfloat1622float2(*reinterpret_cast<const __nv_bfloat162*>(&w3[q]));
                acc[q * 2 + 0] += (f0.x + f1.x) + (f2.x + f3.x);
                acc[q * 2 + 1] += (f0.y + f1.y) + (f2.y + f3.y);
            }
        }
        for (; j < deg; j += 12) {
            int i0 = adj[base + j];
            uint2 p0 = *reinterpret_cast<const uint2*>(src + (size_t)i0 * 40 + chunk * 4);
            const uint32_t* w0 = &p0.x;
            #pragma unroll
            for (int q = 0; q < 2; q++) {
                float2 f0 = __bfloat1622float2(*reinterpret_cast<const __nv_bfloat162*>(&w0[q]));
                acc[q * 2 + 0] += f0.x;
                acc[q * 2 + 1] += f0.y;
            }
        }
        #pragma unroll
        for (int k = 0; k < 4; k++) sacc[rl][chunk][k] = acc[k];
        __syncthreads();
        if (rl == 0) {
            #pragma unroll
            for (int r = 1; r < 12; r++)
                #pragma unroll
                for (int k = 0; k < 4; k++) acc[k] += sacc[r][chunk][k];
            float inv = 1.0f / (float)(deg < 1 ? 1 : deg);
            float4 o;
            o.x = fmaxf(acc[0] * inv, 0.f);
            o.y = fmaxf(acc[1] * inv, 0.f);
            o.z = fmaxf(acc[2] * inv, 0.f);
            o.w = fmaxf(acc[3] * inv, 0.f);
            *reinterpret_cast<float4*>(dst + (size_t)s * 40 + chunk * 4) = o;
        }
        __syncthreads();
    }
}

// ---------------- agg4: v-side segment mean, bf16 source, 40 ch, log_softmax ----------------
__global__ void __launch_bounds__(120)
seg_agg_h40_ls(const __nv_bfloat16* __restrict__ src, const int* __restrict__ cnt,
               const int* __restrict__ adj, float* __restrict__ dst, int nseg) {
    const int tid = threadIdx.x;
    const int chunk = tid % 10;
    const int rl = tid / 10;
    __shared__ float sacc[12][10][4];
    __shared__ float srow[40];
    __shared__ float sbase;

    for (int s = blockIdx.x; s < nseg; s += gridDim.x) {
        int deg = cnt[s]; if (deg > VPAD) deg = VPAD;
        const size_t base = (size_t)s << 7;
        float acc[4] = {0.f, 0.f, 0.f, 0.f};

        int j = rl;
        for (; j + 12 < deg; j += 24) {
            int i0 = adj[base + j], i1 = adj[base + j + 12];
            uint2 p0 = *reinterpret_cast<const uint2*>(src + (size_t)i0 * 40 + chunk * 4);
            uint2 p1 = *reinterpret_cast<const uint2*>(src + (size_t)i1 * 40 + chunk * 4);
            #pragma unroll
            for (int q = 0; q < 2; q++) {
                const uint32_t* w0 = &p0.x; const uint32_t* w1 = &p1.x;
                float2 f0 = __bfloat1622float2(*reinterpret_cast<const __nv_bfloat162*>(&w0[q]));
                float2 f1 = __bfloat1622float2(*reinterpret_cast<const __nv_bfloat162*>(&w1[q]));
                acc[q * 2 + 0] += f0.x + f1.x;
                acc[q * 2 + 1] += f0.y + f1.y;
            }
        }
        for (; j < deg; j += 12) {
            int i0 = adj[base + j];
            uint2 p0 = *reinterpret_cast<const uint2*>(src + (size_t)i0 * 40 + chunk * 4);
            const uint32_t* w0 = &p0.x;
            #pragma unroll
            for (int q = 0; q < 2; q++) {
                float2 f0 = __bfloat1622float2(*reinterpret_cast<const __nv_bfloat162*>(&w0[q]));
                acc[q * 2 + 0] += f0.x;
                acc[q * 2 + 1] += f0.y;
            }
        }
        #pragma unroll
        for (int k = 0; k < 4; k++) sacc[rl][chunk][k] = acc[k];
        __syncthreads();
        if (rl == 0) {
            #pragma unroll
            for (int r = 1; r < 12; r++)
                #pragma unroll
                for (int k = 0; k < 4; k++) acc[k] += sacc[r][chunk][k];
            float inv = 1.0f / (float)(deg < 1 ? 1 : deg);
            srow[chunk * 4 + 0] = acc[0] * inv;
            srow[chunk * 4 + 1] = acc[1] * inv;
            srow[chunk * 4 + 2] = acc[2] * inv;
            srow[chunk * 4 + 3] = acc[3] * inv;
        }
        __syncthreads();
        if (tid == 0) {
            float m = -1e30f;
            #pragma unroll 8
            for (int c = 0; c < 40; c++) m = fmaxf(m, srow[c]);
            float sum = 0.f;
            #pragma unroll 8
            for (int c = 0; c < 40; c++) sum += __expf(srow[c] - m);
            sbase = m + logf(sum);
        }
        __syncthreads();
        if (tid < 40) dst[(size_t)s * 40 + tid] = srow[tid] - sbase;
        __syncthreads();
    }
}

// ---------------- GEMMs (row-major A[M,K] @ W[K,N] -> Out[M,N]) ----------------
template<bool RELU, bool BF16OUT>
__global__ void __launch_bounds__(256)
gemm128(const float* __restrict__ A, const float* __restrict__ W,
        void* __restrict__ OutV, int M) {
    __shared__ float As[64][16];
    __shared__ __align__(16) float Ws[16][128];
    const int tid = threadIdx.x;
    const int c4 = tid % 32;
    const int rg = tid / 32;
    const int row0 = blockIdx.x * 64;
    float4 acc[8];
    #pragma unroll
    for (int i = 0; i < 8; i++) acc[i] = make_float4(0.f, 0.f, 0.f, 0.f);

    for (int k0 = 0; k0 < 128; k0 += 16) {
        {
            int r = tid >> 2, cc = (tid & 3) * 4;
            int gr = row0 + r;
            float4 v = make_float4(0.f, 0.f, 0.f, 0.f);
            if (gr < M) v = *reinterpret_cast<const float4*>(A + (size_t)gr * 128 + k0 + cc);
            *reinterpret_cast<float4*>(&As[r][cc]) = v;
        }
        #pragma unroll
        for (int w = 0; w < 2; w++) {
            int idx = tid + w * 256;
            int kr = idx >> 5, cc = (idx & 31) * 4;
            *reinterpret_cast<float4*>(&Ws[kr][cc]) =
                *reinterpret_cast<const float4*>(W + (size_t)(k0 + kr) * 128 + cc);
        }
        __syncthreads();
        #pragma unroll
        for (int kk = 0; kk < 16; kk++) {
            float4 bv = *reinterpret_cast<const float4*>(&Ws[kk][c4 * 4]);
            #pragma unroll
            for (int i = 0; i < 8; i++) {
                float av = As[rg * 8 + i][kk];
                acc[i].x += av * bv.x; acc[i].y += av * bv.y;
                acc[i].z += av * bv.z; acc[i].w += av * bv.w;
            }
        }
        __syncthreads();
    }
    #pragma unroll
    for (int i = 0; i < 8; i++) {
        int gr = row0 + rg * 8 + i;
        if (gr < M) {
            float4 v = acc[i];
            if (RELU) {
                v.x = fmaxf(v.x, 0.f); v.y = fmaxf(v.y, 0.f);
                v.z = fmaxf(v.z, 0.f); v.w = fmaxf(v.w, 0.f);
            }
            if (BF16OUT) {
                __nv_bfloat16* Out = (__nv_bfloat16*)OutV;
                __nv_bfloat162 a = __floats2bfloat162_rn(v.x, v.y);
                __nv_bfloat162 b = __floats2bfloat162_rn(v.z, v.w);
                uint2 o;
                o.x = *reinterpret_cast<uint32_t*>(&a);
                o.y = *reinterpret_cast<uint32_t*>(&b);
                *reinterpret_cast<uint2*>(Out + (size_t)gr * 128 + c4 * 4) = o;
            } else {
                float* Out = (float*)OutV;
                *reinterpret_cast<float4*>(Out + (size_t)gr * 128 + c4 * 4) = v;
            }
        }
    }
}

template<int K, bool RELU, bool BF16OUT>
__global__ void __launch_bounds__(320)
gemm40(const float* __restrict__ A, const float* __restrict__ W,
       void* __restrict__ OutV, int M) {
    __shared__ float As[64][16];
    __shared__ __align__(16) float Ws[16][40];
    const int tid = threadIdx.x;
    const int c4 = tid % 10;
    const int rg = tid / 10;
    const int row0 = blockIdx.x * 64;
    float4 acc[2];
    acc[0] = make_float4(0.f, 0.f, 0.f, 0.f);
    acc[1] = make_float4(0.f, 0.f, 0.f, 0.f);

    for (int k0 = 0; k0 < K; k0 += 16) {
        if (tid < 256) {
            int r = tid >> 2, cc = (tid & 3) * 4;
            int gr = row0 + r;
            float4 v = make_float4(0.f, 0.f, 0.f, 0.f);
            if (gr < M && (k0 + cc) < K)
                v = *reinterpret_cast<const float4*>(A + (size_t)gr * K + k0 + cc);
            *reinterpret_cast<float4*>(&As[r][cc]) = v;
        }
        if (tid < 160) {
            int kr = tid / 10, cc = (tid % 10) * 4;
            float4 v = make_float4(0.f, 0.f, 0.f, 0.f);
            if ((k0 + kr) < K)
                v = *reinterpret_cast<const float4*>(W + (size_t)(k0 + kr) * 40 + cc);
            *reinterpret_cast<float4*>(&Ws[kr][cc]) = v;
        }
        __syncthreads();
        #pragma unroll
        for (int kk = 0; kk < 16; kk++) {
            float4 bv = *reinterpret_cast<const float4*>(&Ws[kk][c4 * 4]);
            #pragma unroll
            for (int i = 0; i < 2; i++) {
                float av = As[rg * 2 + i][kk];
                acc[i].x += av * bv.x; acc[i].y += av * bv.y;
                acc[i].z += av * bv.z; acc[i].w += av * bv.w;
            }
        }
        __syncthreads();
    }
    #pragma unroll
    for (int i = 0; i < 2; i++) {
        int gr = row0 + rg * 2 + i;
        if (gr < M) {
            float4 v = acc[i];
            if (RELU) {
                v.x = fmaxf(v.x, 0.f); v.y = fmaxf(v.y, 0.f);
                v.z = fmaxf(v.z, 0.f); v.w = fmaxf(v.w, 0.f);
            }
            if (BF16OUT) {
                __nv_bfloat16* Out = (__nv_bfloat16*)OutV;
                __nv_bfloat162 a = __floats2bfloat162_rn(v.x, v.y);
                __nv_bfloat162 b = __floats2bfloat162_rn(v.z, v.w);
                uint2 o;
                o.x = *reinterpret_cast<uint32_t*>(&a);
                o.y = *reinterpret_cast<uint32_t*>(&b);
                *reinterpret_cast<uint2*>(Out + (size_t)gr * 40 + c4 * 4) = o;
            } else {
                float* Out = (float*)OutV;
                *reinterpret_cast<float4*>(Out + (size_t)gr * 40 + c4 * 4) = v;
            }
        }
    }
}

// ---------------- host ----------------
extern "C" void kernel_launch(void* const* d_in, const int* in_sizes, int n_in,
                              void* d_out, int out_size) {
    const float* x     = (const float*)d_in[0];
    const int*   v_ids = (const int*)  d_in[1];
    const int*   e_ids = (const int*)  d_in[2];
    const float* w1a   = (const float*)d_in[3];
    const float* w1b   = (const float*)d_in[4];
    const float* w2a   = (const float*)d_in[5];
    const float* w2b   = (const float*)d_in[6];
    const float* bng   = (const float*)d_in[7];
    const float* bnb   = (const float*)d_in[8];
    const float* bnm   = (const float*)d_in[9];
    const float* bnv   = (const float*)d_in[10];
    float* out = (float*)d_out;
    const int nnz = in_sizes[1];

    void* p;
    cudaGetSymbolAddress(&p, g_ecnt);  int* ecnt  = (int*)p;
    cudaGetSymbolAddress(&p, g_vcnt);  int* vcnt  = (int*)p;
    cudaGetSymbolAddress(&p, g_eadj);  int* eadj  = (int*)p;
    cudaGetSymbolAddress(&p, g_vadj);  int* vadj  = (int*)p;
    cudaGetSymbolAddress(&p, g_ebuf);  float* ebuf  = (float*)p;
    cudaGetSymbolAddress(&p, g_ebuf2); float* ebuf2 = (float*)p;
    cudaGetSymbolAddress(&p, g_vbuf);  float* vbuf  = (float*)p;
    cudaGetSymbolAddress(&p, g_xh);    __nv_bfloat16* xh   = (__nv_bfloat16*)p;
    cudaGetSymbolAddress(&p, g_eh);    __nv_bfloat16* eh   = (__nv_bfloat16*)p;
    cudaGetSymbolAddress(&p, g_vb2h);  __nv_bfloat16* vb2h = (__nv_bfloat16*)p;
    cudaGetSymbolAddress(&p, g_e40h);  __nv_bfloat16* e40h = (__nv_bfloat16*)p;

    // ---- padded adjacency build ----
    zero_counts<<<256, 256>>>(ecnt, NE, vcnt, NV);
    build_padded<<<2048, 256>>>(v_ids, e_ids, ecnt, vcnt, eadj, vadj, nnz);
    cvt_bf16<<<(NV * CH / 4 + 255) / 256, 256>>>(x, xh, NV * CH);

    // ---- layer 1 ----
    seg_agg_h128<<<NE, 128>>>(xh, ecnt, eadj, ebuf, NE);
    gemm128<true,  false><<<(NE + 63) / 64, 256>>>(ebuf,  w1a, ebuf2, NE);
    gemm128<false, true ><<<(NE + 63) / 64, 256>>>(ebuf2, w1b, eh,    NE);   // -> bf16 for agg2
    seg_agg2_h128_bn<<<(NV + 7) / 8, 256>>>(eh, vcnt, vadj, vbuf, NV, bng, bnb, bnm, bnv);

    // ---- layer 2 ----
    gemm40<128, false, true><<<(NV + 63) / 64, 320>>>(vbuf, w2a, vb2h, NV);
    seg_agg_h40<<<NE, 120>>>(vb2h, ecnt, eadj, ebuf2, NE);                   // fp32 out (NE x 40)
    gemm40<40, false, true><<<(NE + 63) / 64, 320>>>(ebuf2, w2b, e40h, NE);  // -> bf16 for agg4
    seg_agg_h40_ls<<<NV, 120>>>(e40h, vcnt, vadj, out, NV);
}

// round 7
// speedup vs baseline: 1.0767x; 1.0767x over previous
#include <cuda_runtime.h>
#include <cuda_bf16.h>
#include <math.h>
#include <stdint.h>

#define NV 100000
#define NE 20000
#define CH 128
#define NCLS 40
#define BN_EPS 1e-5f
#define EPAD 256   // max hyperedge degree slot (mean 160, sigma 12.6)
#define VPAD 128   // max vertex degree slot (mean 32, sigma 5.7)

// ---------------- scratch (device globals; no cudaMalloc allowed) ----------------
__device__ static float g_ebuf [(size_t)NE * CH];          // 10.24 MB
__device__ static float g_ebuf2[(size_t)NE * CH];          // 10.24 MB
__device__ static float g_vbuf [(size_t)NV * CH];          // 51.2 MB
__device__ static __nv_bfloat16 g_xh   [(size_t)NV * CH];  // 25.6 MB (x in bf16)
__device__ static __nv_bfloat16 g_vb2h [(size_t)NV * NCLS];// 8 MB
__device__ static int   g_ecnt[NE];
__device__ static int   g_vcnt[NV];
__device__ static int   g_eadj[(size_t)NE * EPAD];         // 20.48 MB
__device__ static int   g_vadj[(size_t)NV * VPAD];         // 51.2 MB

// ---------------- prelude ----------------
__global__ void zero_counts(int* e, int ne, int* v, int nv) {
    int total = ne + nv;
    for (int i = blockIdx.x * blockDim.x + threadIdx.x; i < total; i += gridDim.x * blockDim.x) {
        if (i < ne) e[i] = 0; else v[i - ne] = 0;
    }
}

// Single-pass padded adjacency build (rank = atomic return value).
__global__ void build_padded(const int* __restrict__ v_ids, const int* __restrict__ e_ids,
                             int* ecnt, int* vcnt,
                             int* __restrict__ eadj, int* __restrict__ vadj, int nnz) {
    for (int i = blockIdx.x * blockDim.x + threadIdx.x; i < nnz; i += gridDim.x * blockDim.x) {
        int e = e_ids[i], v = v_ids[i];
        int re = atomicAdd(&ecnt[e], 1);
        if (re < EPAD) eadj[((size_t)e << 8) + re] = v;
        int rv = atomicAdd(&vcnt[v], 1);
        if (rv < VPAD) vadj[((size_t)v << 7) + rv] = e;
    }
}

// fp32 -> bf16 elementwise (n multiple of 4)
__global__ void cvt_bf16(const float* __restrict__ src, __nv_bfloat16* __restrict__ dst, int n) {
    int i = (blockIdx.x * blockDim.x + threadIdx.x) * 4;
    if (i < n) {
        float4 f = *reinterpret_cast<const float4*>(src + i);
        __nv_bfloat162 a = __floats2bfloat162_rn(f.x, f.y);
        __nv_bfloat162 b = __floats2bfloat162_rn(f.z, f.w);
        uint2 o;
        o.x = *reinterpret_cast<uint32_t*>(&a);
        o.y = *reinterpret_cast<uint32_t*>(&b);
        *reinterpret_cast<uint2*>(dst + i) = o;
    }
}

__device__ __forceinline__ void acc_bf16x8(float* acc, uint4 p) {
    const uint32_t* w = &p.x;
    #pragma unroll
    for (int q = 0; q < 4; q++) {
        float2 f = __bfloat1622float2(*reinterpret_cast<const __nv_bfloat162*>(&w[q]));
        acc[q * 2 + 0] += f.x;
        acc[q * 2 + 1] += f.y;
    }
}

// ---------------- agg1: e-side segment mean, bf16 source, 128 ch ----------------
// Block per segment; 16 threads/row, 8 rows in flight, unroll x4 (MLP=4/thread).
__global__ void __launch_bounds__(128)
seg_agg_h128(const __nv_bfloat16* __restrict__ src, const int* __restrict__ cnt,
             const int* __restrict__ adj, float* __restrict__ dst, int nseg) {
    const int tid = threadIdx.x;
    const int chunk = tid % 16;
    const int rl = tid / 16;
    __shared__ float sacc[8][16][8];

    for (int s = blockIdx.x; s < nseg; s += gridDim.x) {
        int deg = cnt[s]; if (deg > EPAD) deg = EPAD;
        const size_t base = (size_t)s << 8;
        float acc[8];
        #pragma unroll
        for (int k = 0; k < 8; k++) acc[k] = 0.f;

        int j = rl;
        for (; j + 24 < deg; j += 32) {
            int i0 = adj[base + j],      i1 = adj[base + j + 8];
            int i2 = adj[base + j + 16], i3 = adj[base + j + 24];
            uint4 p0 = *reinterpret_cast<const uint4*>(src + (size_t)i0 * 128 + chunk * 8);
            uint4 p1 = *reinterpret_cast<const uint4*>(src + (size_t)i1 * 128 + chunk * 8);
            uint4 p2 = *reinterpret_cast<const uint4*>(src + (size_t)i2 * 128 + chunk * 8);
            uint4 p3 = *reinterpret_cast<const uint4*>(src + (size_t)i3 * 128 + chunk * 8);
            acc_bf16x8(acc, p0);
            acc_bf16x8(acc, p1);
            acc_bf16x8(acc, p2);
            acc_bf16x8(acc, p3);
        }
        for (; j < deg; j += 8) {
            int i0 = adj[base + j];
            uint4 p0 = *reinterpret_cast<const uint4*>(src + (size_t)i0 * 128 + chunk * 8);
            acc_bf16x8(acc, p0);
        }
        #pragma unroll
        for (int k = 0; k < 8; k++) sacc[rl][chunk][k] = acc[k];
        __syncthreads();
        if (rl == 0) {
            #pragma unroll
            for (int r = 1; r < 8; r++)
                #pragma unroll
                for (int k = 0; k < 8; k++) acc[k] += sacc[r][chunk][k];
            float inv = 1.0f / (float)(deg < 1 ? 1 : deg);
            #pragma unroll
            for (int k = 0; k < 8; k++) acc[k] *= inv;
            float4 o0 = make_float4(acc[0], acc[1], acc[2], acc[3]);
            float4 o1 = make_float4(acc[4], acc[5], acc[6], acc[7]);
            *reinterpret_cast<float4*>(dst + (size_t)s * 128 + chunk * 8) = o0;
            *reinterpret_cast<float4*>(dst + (size_t)s * 128 + chunk * 8 + 4) = o1;
        }
        __syncthreads();
    }
}

// ---------------- agg2: v-side warp-per-segment mean, fp32 128 ch, relu+BN ----------------
// Unroll x8 (8 independent index+payload loads in flight per lane).
__global__ void __launch_bounds__(256)
seg_agg_w128_bn(const float* __restrict__ src, const int* __restrict__ cnt,
                const int* __restrict__ adj, float* __restrict__ dst, int nseg,
                const float* __restrict__ bng, const float* __restrict__ bnb,
                const float* __restrict__ bnm, const float* __restrict__ bnv) {
    const int lane = threadIdx.x & 31;
    const int wid = (blockIdx.x * (blockDim.x >> 5)) + (threadIdx.x >> 5);
    const int nw = gridDim.x * (blockDim.x >> 5);

    float4 ga = *reinterpret_cast<const float4*>(bng + lane * 4);
    float4 be = *reinterpret_cast<const float4*>(bnb + lane * 4);
    float4 mu = *reinterpret_cast<const float4*>(bnm + lane * 4);
    float4 va = *reinterpret_cast<const float4*>(bnv + lane * 4);
    float4 sc, sh;
    sc.x = rsqrtf(va.x + BN_EPS) * ga.x; sh.x = be.x - mu.x * sc.x;
    sc.y = rsqrtf(va.y + BN_EPS) * ga.y; sh.y = be.y - mu.y * sc.y;
    sc.z = rsqrtf(va.z + BN_EPS) * ga.z; sh.z = be.z - mu.z * sc.z;
    sc.w = rsqrtf(va.w + BN_EPS) * ga.w; sh.w = be.w - mu.w * sc.w;

    for (int s = wid; s < nseg; s += nw) {
        int deg = cnt[s]; if (deg > VPAD) deg = VPAD;
        const size_t base = (size_t)s << 7;
        float4 acc = make_float4(0.f, 0.f, 0.f, 0.f);
        int j = 0;
        for (; j + 7 < deg; j += 8) {
            int i0 = adj[base + j],     i1 = adj[base + j + 1];
            int i2 = adj[base + j + 2], i3 = adj[base + j + 3];
            int i4 = adj[base + j + 4], i5 = adj[base + j + 5];
            int i6 = adj[base + j + 6], i7 = adj[base + j + 7];
            float4 a0 = *reinterpret_cast<const float4*>(src + (size_t)i0 * 128 + lane * 4);
            float4 a1 = *reinterpret_cast<const float4*>(src + (size_t)i1 * 128 + lane * 4);
            float4 a2 = *reinterpret_cast<const float4*>(src + (size_t)i2 * 128 + lane * 4);
            float4 a3 = *reinterpret_cast<const float4*>(src + (size_t)i3 * 128 + lane * 4);
            float4 a4 = *reinterpret_cast<const float4*>(src + (size_t)i4 * 128 + lane * 4);
            float4 a5 = *reinterpret_cast<const float4*>(src + (size_t)i5 * 128 + lane * 4);
            float4 a6 = *reinterpret_cast<const float4*>(src + (size_t)i6 * 128 + lane * 4);
            float4 a7 = *reinterpret_cast<const float4*>(src + (size_t)i7 * 128 + lane * 4);
            acc.x += ((a0.x + a1.x) + (a2.x + a3.x)) + ((a4.x + a5.x) + (a6.x + a7.x));
            acc.y += ((a0.y + a1.y) + (a2.y + a3.y)) + ((a4.y + a5.y) + (a6.y + a7.y));
            acc.z += ((a0.z + a1.z) + (a2.z + a3.z)) + ((a4.z + a5.z) + (a6.z + a7.z));
            acc.w += ((a0.w + a1.w) + (a2.w + a3.w)) + ((a4.w + a5.w) + (a6.w + a7.w));
        }
        for (; j + 3 < deg; j += 4) {
            int i0 = adj[base + j], i1 = adj[base + j + 1];
            int i2 = adj[base + j + 2], i3 = adj[base + j + 3];
            float4 a0 = *reinterpret_cast<const float4*>(src + (size_t)i0 * 128 + lane * 4);
            float4 a1 = *reinterpret_cast<const float4*>(src + (size_t)i1 * 128 + lane * 4);
            float4 a2 = *reinterpret_cast<const float4*>(src + (size_t)i2 * 128 + lane * 4);
            float4 a3 = *reinterpret_cast<const float4*>(src + (size_t)i3 * 128 + lane * 4);
            acc.x += (a0.x + a1.x) + (a2.x + a3.x);
            acc.y += (a0.y + a1.y) + (a2.y + a3.y);
            acc.z += (a0.z + a1.z) + (a2.z + a3.z);
            acc.w += (a0.w + a1.w) + (a2.w + a3.w);
        }
        for (; j < deg; j++) {
            int i0 = adj[base + j];
            float4 a0 = *reinterpret_cast<const float4*>(src + (size_t)i0 * 128 + lane * 4);
            acc.x += a0.x; acc.y += a0.y; acc.z += a0.z; acc.w += a0.w;
        }
        float inv = 1.0f / (float)(deg < 1 ? 1 : deg);
        float4 o;
        o.x = fmaxf(acc.x * inv, 0.f) * sc.x + sh.x;
        o.y = fmaxf(acc.y * inv, 0.f) * sc.y + sh.y;
        o.z = fmaxf(acc.z * inv, 0.f) * sc.z + sh.z;
        o.w = fmaxf(acc.w * inv, 0.f) * sc.w + sh.w;
        *reinterpret_cast<float4*>(dst + (size_t)s * 128 + lane * 4) = o;
    }
}

// ---------------- agg3: e-side segment mean, bf16 source, 40 ch, relu ----------------
__global__ void __launch_bounds__(120)
seg_agg_h40(const __nv_bfloat16* __restrict__ src, const int* __restrict__ cnt,
            const int* __restrict__ adj, float* __restrict__ dst, int nseg) {
    const int tid = threadIdx.x;
    const int chunk = tid % 10;
    const int rl = tid / 10;
    __shared__ float sacc[12][10][4];

    for (int s = blockIdx.x; s < nseg; s += gridDim.x) {
        int deg = cnt[s]; if (deg > EPAD) deg = EPAD;
        const size_t base = (size_t)s << 8;
        float acc[4] = {0.f, 0.f, 0.f, 0.f};

        int j = rl;
        for (; j + 3 * 12 < deg; j += 4 * 12) {
            int i0 = adj[base + j],      i1 = adj[base + j + 12];
            int i2 = adj[base + j + 24], i3 = adj[base + j + 36];
            uint2 p0 = *reinterpret_cast<const uint2*>(src + (size_t)i0 * 40 + chunk * 4);
            uint2 p1 = *reinterpret_cast<const uint2*>(src + (size_t)i1 * 40 + chunk * 4);
            uint2 p2 = *reinterpret_cast<const uint2*>(src + (size_t)i2 * 40 + chunk * 4);
            uint2 p3 = *reinterpret_cast<const uint2*>(src + (size_t)i3 * 40 + chunk * 4);
            #pragma unroll
            for (int q = 0; q < 2; q++) {
                const uint32_t* w0 = &p0.x; const uint32_t* w1 = &p1.x;
                const uint32_t* w2 = &p2.x; const uint32_t* w3 = &p3.x;
                float2 f0 = __bfloat1622float2(*reinterpret_cast<const __nv_bfloat162*>(&w0[q]));
                float2 f1 = __bfloat1622float2(*reinterpret_cast<const __nv_bfloat162*>(&w1[q]));
                float2 f2 = __bfloat1622float2(*reinterpret_cast<const __nv_bfloat162*>(&w2[q]));
                float2 f3 = __bfloat1622float2(*reinterpret_cast<const __nv_bfloat162*>(&w3[q]));
                acc[q * 2 + 0] += (f0.x + f1.x) + (f2.x + f3.x);
                acc[q * 2 + 1] += (f0.y + f1.y) + (f2.y + f3.y);
            }
        }
        for (; j < deg; j += 12) {
            int i0 = adj[base + j];
            uint2 p0 = *reinterpret_cast<const uint2*>(src + (size_t)i0 * 40 + chunk * 4);
            const uint32_t* w0 = &p0.x;
            #pragma unroll
            for (int q = 0; q < 2; q++) {
                float2 f0 = __bfloat1622float2(*reinterpret_cast<const __nv_bfloat162*>(&w0[q]));
                acc[q * 2 + 0] += f0.x;
                acc[q * 2 + 1] += f0.y;
            }
        }
        #pragma unroll
        for (int k = 0; k < 4; k++) sacc[rl][chunk][k] = acc[k];
        __syncthreads();
        if (rl == 0) {
            #pragma unroll
            for (int r = 1; r < 12; r++)
                #pragma unroll
                for (int k = 0; k < 4; k++) acc[k] += sacc[r][chunk][k];
            float inv = 1.0f / (float)(deg < 1 ? 1 : deg);
            float4 o;
            o.x = fmaxf(acc[0] * inv, 0.f);
            o.y = fmaxf(acc[1] * inv, 0.f);
            o.z = fmaxf(acc[2] * inv, 0.f);
            o.w = fmaxf(acc[3] * inv, 0.f);
            *reinterpret_cast<float4*>(dst + (size_t)s * 40 + chunk * 4) = o;
        }
        __syncthreads();
    }
}

// ---------------- agg4: v-side segment mean, fp32 40 ch, log_softmax ----------------
__global__ void __launch_bounds__(120)
seg_agg40_ls(const float* __restrict__ src, const int* __restrict__ cnt,
             const int* __restrict__ adj, float* __restrict__ dst, int nseg) {
    const int tid = threadIdx.x;
    const int chunk = tid % 10;
    const int rl = tid / 10;
    __shared__ float4 sacc[12][10];
    __shared__ float srow[40];
    __shared__ float sbase;

    for (int s = blockIdx.x; s < nseg; s += gridDim.x) {
        int deg = cnt[s]; if (deg > VPAD) deg = VPAD;
        const size_t base = (size_t)s << 7;
        float4 acc = make_float4(0.f, 0.f, 0.f, 0.f);
        int j = rl;
        for (; j + 12 < deg; j += 24) {
            int i0 = adj[base + j], i1 = adj[base + j + 12];
            float4 a0 = *reinterpret_cast<const float4*>(src + (size_t)i0 * 40 + chunk * 4);
            float4 a1 = *reinterpret_cast<const float4*>(src + (size_t)i1 * 40 + chunk * 4);
            acc.x += a0.x + a1.x; acc.y += a0.y + a1.y;
            acc.z += a0.z + a1.z; acc.w += a0.w + a1.w;
        }
        for (; j < deg; j += 12) {
            int i0 = adj[base + j];
            float4 a0 = *reinterpret_cast<const float4*>(src + (size_t)i0 * 40 + chunk * 4);
            acc.x += a0.x; acc.y += a0.y; acc.z += a0.z; acc.w += a0.w;
        }
        sacc[rl][chunk] = acc;
        __syncthreads();
        if (rl == 0) {
            #pragma unroll
            for (int r = 1; r < 12; r++) {
                float4 o = sacc[r][chunk];
                acc.x += o.x; acc.y += o.y; acc.z += o.z; acc.w += o.w;
            }
            float inv = 1.0f / (float)(deg < 1 ? 1 : deg);
            srow[chunk * 4 + 0] = acc.x * inv;
            srow[chunk * 4 + 1] = acc.y * inv;
            srow[chunk * 4 + 2] = acc.z * inv;
            srow[chunk * 4 + 3] = acc.w * inv;
        }
        __syncthreads();
        if (tid == 0) {
            float m = -1e30f;
            #pragma unroll 8
            for (int c = 0; c < 40; c++) m = fmaxf(m, srow[c]);
            float sum = 0.f;
            #pragma unroll 8
            for (int c = 0; c < 40; c++) sum += __expf(srow[c] - m);
            sbase = m + logf(sum);
        }
        __syncthreads();
        if (tid < 40) dst[(size_t)s * 40 + tid] = srow[tid] - sbase;
        __syncthreads();
    }
}

// ---------------- GEMMs (row-major A[M,K] @ W[K,N] -> Out[M,N]) ----------------
template<bool RELU>
__global__ void __launch_bounds__(256)
gemm128(const float* __restrict__ A, const float* __restrict__ W,
        float* __restrict__ Out, int M) {
    __shared__ float As[64][16];
    __shared__ __align__(16) float Ws[16][128];
    const int tid = threadIdx.x;
    const int c4 = tid % 32;
    const int rg = tid / 32;
    const int row0 = blockIdx.x * 64;
    float4 acc[8];
    #pragma unroll
    for (int i = 0; i < 8; i++) acc[i] = make_float4(0.f, 0.f, 0.f, 0.f);

    for (int k0 = 0; k0 < 128; k0 += 16) {
        {
            int r = tid >> 2, cc = (tid & 3) * 4;
            int gr = row0 + r;
            float4 v = make_float4(0.f, 0.f, 0.f, 0.f);
            if (gr < M) v = *reinterpret_cast<const float4*>(A + (size_t)gr * 128 + k0 + cc);
            *reinterpret_cast<float4*>(&As[r][cc]) = v;
        }
        #pragma unroll
        for (int w = 0; w < 2; w++) {
            int idx = tid + w * 256;
            int kr = idx >> 5, cc = (idx & 31) * 4;
            *reinterpret_cast<float4*>(&Ws[kr][cc]) =
                *reinterpret_cast<const float4*>(W + (size_t)(k0 + kr) * 128 + cc);
        }
        __syncthreads();
        #pragma unroll
        for (int kk = 0; kk < 16; kk++) {
            float4 bv = *reinterpret_cast<const float4*>(&Ws[kk][c4 * 4]);
            #pragma unroll
            for (int i = 0; i < 8; i++) {
                float av = As[rg * 8 + i][kk];
                acc[i].x += av * bv.x; acc[i].y += av * bv.y;
                acc[i].z += av * bv.z; acc[i].w += av * bv.w;
            }
        }
        __syncthreads();
    }
    #pragma unroll
    for (int i = 0; i < 8; i++) {
        int gr = row0 + rg * 8 + i;
        if (gr < M) {
            float4 v = acc[i];
            if (RELU) {
                v.x = fmaxf(v.x, 0.f); v.y = fmaxf(v.y, 0.f);
                v.z = fmaxf(v.z, 0.f); v.w = fmaxf(v.w, 0.f);
            }
            *reinterpret_cast<float4*>(Out + (size_t)gr * 128 + c4 * 4) = v;
        }
    }
}

template<int K, bool RELU, bool BF16OUT>
__global__ void __launch_bounds__(320)
gemm40(const float* __restrict__ A, const float* __restrict__ W,
       void* __restrict__ OutV, int M) {
    __shared__ float As[64][16];
    __shared__ __align__(16) float Ws[16][40];
    const int tid = threadIdx.x;
    const int c4 = tid % 10;
    const int rg = tid / 10;
    const int row0 = blockIdx.x * 64;
    float4 acc[2];
    acc[0] = make_float4(0.f, 0.f, 0.f, 0.f);
    acc[1] = make_float4(0.f, 0.f, 0.f, 0.f);

    for (int k0 = 0; k0 < K; k0 += 16) {
        if (tid < 256) {
            int r = tid >> 2, cc = (tid & 3) * 4;
            int gr = row0 + r;
            float4 v = make_float4(0.f, 0.f, 0.f, 0.f);
            if (gr < M && (k0 + cc) < K)
                v = *reinterpret_cast<const float4*>(A + (size_t)gr * K + k0 + cc);
            *reinterpret_cast<float4*>(&As[r][cc]) = v;
        }
        if (tid < 160) {
            int kr = tid / 10, cc = (tid % 10) * 4;
            float4 v = make_float4(0.f, 0.f, 0.f, 0.f);
            if ((k0 + kr) < K)
                v = *reinterpret_cast<const float4*>(W + (size_t)(k0 + kr) * 40 + cc);
            *reinterpret_cast<float4*>(&Ws[kr][cc]) = v;
        }
        __syncthreads();
        #pragma unroll
        for (int kk = 0; kk < 16; kk++) {
            float4 bv = *reinterpret_cast<const float4*>(&Ws[kk][c4 * 4]);
            #pragma unroll
            for (int i = 0; i < 2; i++) {
                float av = As[rg * 2 + i][kk];
                acc[i].x += av * bv.x; acc[i].y += av * bv.y;
                acc[i].z += av * bv.z; acc[i].w += av * bv.w;
            }
        }
        __syncthreads();
    }
    #pragma unroll
    for (int i = 0; i < 2; i++) {
        int gr = row0 + rg * 2 + i;
        if (gr < M) {
            float4 v = acc[i];
            if (RELU) {
                v.x = fmaxf(v.x, 0.f); v.y = fmaxf(v.y, 0.f);
                v.z = fmaxf(v.z, 0.f); v.w = fmaxf(v.w, 0.f);
            }
            if (BF16OUT) {
                __nv_bfloat16* Out = (__nv_bfloat16*)OutV;
                __nv_bfloat162 a = __floats2bfloat162_rn(v.x, v.y);
                __nv_bfloat162 b = __floats2bfloat162_rn(v.z, v.w);
                uint2 o;
                o.x = *reinterpret_cast<uint32_t*>(&a);
                o.y = *reinterpret_cast<uint32_t*>(&b);
                *reinterpret_cast<uint2*>(Out + (size_t)gr * 40 + c4 * 4) = o;
            } else {
                float* Out = (float*)OutV;
                *reinterpret_cast<float4*>(Out + (size_t)gr * 40 + c4 * 4) = v;
            }
        }
    }
}

// ---------------- host ----------------
extern "C" void kernel_launch(void* const* d_in, const int* in_sizes, int n_in,
                              void* d_out, int out_size) {
    const float* x     = (const float*)d_in[0];
    const int*   v_ids = (const int*)  d_in[1];
    const int*   e_ids = (const int*)  d_in[2];
    const float* w1a   = (const float*)d_in[3];
    const float* w1b   = (const float*)d_in[4];
    const float* w2a   = (const float*)d_in[5];
    const float* w2b   = (const float*)d_in[6];
    const float* bng   = (const float*)d_in[7];
    const float* bnb   = (const float*)d_in[8];
    const float* bnm   = (const float*)d_in[9];
    const float* bnv   = (const float*)d_in[10];
    float* out = (float*)d_out;
    const int nnz = in_sizes[1];

    void* p;
    cudaGetSymbolAddress(&p, g_ecnt);  int* ecnt  = (int*)p;
    cudaGetSymbolAddress(&p, g_vcnt);  int* vcnt  = (int*)p;
    cudaGetSymbolAddress(&p, g_eadj);  int* eadj  = (int*)p;
    cudaGetSymbolAddress(&p, g_vadj);  int* vadj  = (int*)p;
    cudaGetSymbolAddress(&p, g_ebuf);  float* ebuf  = (float*)p;
    cudaGetSymbolAddress(&p, g_ebuf2); float* ebuf2 = (float*)p;
    cudaGetSymbolAddress(&p, g_vbuf);  float* vbuf  = (float*)p;
    cudaGetSymbolAddress(&p, g_xh);    __nv_bfloat16* xh   = (__nv_bfloat16*)p;
    cudaGetSymbolAddress(&p, g_vb2h);  __nv_bfloat16* vb2h = (__nv_bfloat16*)p;

    // ---- padded adjacency build ----
    zero_counts<<<256, 256>>>(ecnt, NE, vcnt, NV);
    build_padded<<<2048, 256>>>(v_ids, e_ids, ecnt, vcnt, eadj, vadj, nnz);
    cvt_bf16<<<(NV * CH / 4 + 255) / 256, 256>>>(x, xh, NV * CH);

    // ---- layer 1 ----
    seg_agg_h128<<<NE, 128>>>(xh, ecnt, eadj, ebuf, NE);
    gemm128<true ><<<(NE + 63) / 64, 256>>>(ebuf,  w1a, ebuf2, NE);
    gemm128<false><<<(NE + 63) / 64, 256>>>(ebuf2, w1b, ebuf,  NE);
    seg_agg_w128_bn<<<(NV + 7) / 8, 256>>>(ebuf, vcnt, vadj, vbuf, NV, bng, bnb, bnm, bnv);

    // ---- layer 2 ----
    gemm40<128, false, true><<<(NV + 63) / 64, 320>>>(vbuf, w2a, vb2h, NV);
    seg_agg_h40<<<NE, 120>>>(vb2h, ecnt, eadj, ebuf2, NE);
    gemm40<40, false, false><<<(NE + 63) / 64, 320>>>(ebuf2, w2b, ebuf, NE);
    seg_agg40_ls<<<NV, 120>>>(ebuf, vcnt, vadj, out, NV);
}